// round 1
// baseline (speedup 1.0000x reference)
#include <cuda_runtime.h>

// VolGeoNet trilinear interpolation.
// Inputs (metadata order): x [B,3] f32, grid_value [N1^3,1] f32, grid_feature [N1^3,256] f32.
// Output: concat(out [B,1], feat [B,256]) as float, out first.

#define N_GRID 64
#define N1 65
#define W_FEAT 256

__global__ void __launch_bounds__(256) trilerp_kernel(
    const float* __restrict__ x,
    const float* __restrict__ gv,
    const float* __restrict__ gf,
    float* __restrict__ out_val,   // [B]
    float* __restrict__ out_feat,  // [B, 256]
    int B)
{
    const int warp_global = (blockIdx.x * blockDim.x + threadIdx.x) >> 5;
    const int lane = threadIdx.x & 31;
    if (warp_global >= B) return;

    // Broadcast point load (all lanes same address -> one L1 transaction)
    const float px = x[warp_global * 3 + 0];
    const float py = x[warp_global * 3 + 1];
    const float pz = x[warp_global * 3 + 2];

    // rel = (x - (-1)) * (64/2)
    const float rx = (px + 1.0f) * 32.0f;
    const float ry = (py + 1.0f) * 32.0f;
    const float rz = (pz + 1.0f) * 32.0f;

    const bool valid = (rx >= 0.0f) && (rx <= 64.0f) &&
                       (ry >= 0.0f) && (ry <= 64.0f) &&
                       (rz >= 0.0f) && (rz <= 64.0f);
    const float vmask = valid ? 1.0f : 0.0f;

    int ix = (int)floorf(rx); ix = ix < 0 ? 0 : (ix > N_GRID - 1 ? N_GRID - 1 : ix);
    int iy = (int)floorf(ry); iy = iy < 0 ? 0 : (iy > N_GRID - 1 ? N_GRID - 1 : iy);
    int iz = (int)floorf(rz); iz = iz < 0 ? 0 : (iz > N_GRID - 1 ? N_GRID - 1 : iz);

    const float tx = rx - (float)ix;
    const float ty = ry - (float)iy;
    const float tz = rz - (float)iz;

    const int base = (ix * N1 + iy) * N1 + iz;

    // Corner c = ox*4 + oy*2 + oz
    const float wx0 = 1.0f - tx, wy0 = 1.0f - ty, wz0 = 1.0f - tz;
    float w[8];
    w[0] = wx0 * wy0 * wz0;
    w[1] = wx0 * wy0 * tz;
    w[2] = wx0 * ty  * wz0;
    w[3] = wx0 * ty  * tz;
    w[4] = tx  * wy0 * wz0;
    w[5] = tx  * wy0 * tz;
    w[6] = tx  * ty  * wz0;
    w[7] = tx  * ty  * tz;

    const int offs[8] = {
        0, 1, N1, N1 + 1,
        N1 * N1, N1 * N1 + 1, N1 * N1 + N1, N1 * N1 + N1 + 1
    };

    // grid_value gather: lanes 0..7 each own one corner, butterfly-reduce.
    float gvv = 0.0f;
    if (lane < 8) {
        gvv = w[lane] * __ldg(gv + (base + offs[lane]));
    }
    gvv += __shfl_xor_sync(0xffffffffu, gvv, 4);
    gvv += __shfl_xor_sync(0xffffffffu, gvv, 2);
    gvv += __shfl_xor_sync(0xffffffffu, gvv, 1);
    if (lane == 0) out_val[warp_global] = gvv * vmask;

    // Feature blend: each lane accumulates 8 channels (two float4 slots).
    float a0 = 0.f, a1 = 0.f, a2 = 0.f, a3 = 0.f;
    float b0 = 0.f, b1 = 0.f, b2 = 0.f, b3 = 0.f;

#pragma unroll
    for (int c = 0; c < 8; c++) {
        const float4* row = (const float4*)(gf + (size_t)(base + offs[c]) * W_FEAT);
        const float4 fa = __ldg(row + lane);
        const float4 fb = __ldg(row + lane + 32);
        const float wc = w[c];
        a0 = fmaf(wc, fa.x, a0);
        a1 = fmaf(wc, fa.y, a1);
        a2 = fmaf(wc, fa.z, a2);
        a3 = fmaf(wc, fa.w, a3);
        b0 = fmaf(wc, fb.x, b0);
        b1 = fmaf(wc, fb.y, b1);
        b2 = fmaf(wc, fb.z, b2);
        b3 = fmaf(wc, fb.w, b3);
    }

    float4* frow = (float4*)(out_feat + (size_t)warp_global * W_FEAT);
    frow[lane]      = make_float4(a0 * vmask, a1 * vmask, a2 * vmask, a3 * vmask);
    frow[lane + 32] = make_float4(b0 * vmask, b1 * vmask, b2 * vmask, b3 * vmask);
}

extern "C" void kernel_launch(void* const* d_in, const int* in_sizes, int n_in,
                              void* d_out, int out_size)
{
    const float* x  = (const float*)d_in[0];
    const float* gv = (const float*)d_in[1];
    const float* gf = (const float*)d_in[2];
    float* out = (float*)d_out;

    const int B = in_sizes[0] / 3;
    float* out_val  = out;        // [B]
    float* out_feat = out + B;    // [B, 256]

    const int threads = 256;             // 8 warps = 8 points per block
    const int warps_per_block = threads / 32;
    const int blocks = (B + warps_per_block - 1) / warps_per_block;
    trilerp_kernel<<<blocks, threads>>>(x, gv, gf, out_val, out_feat, B);
}

// round 2
// speedup vs baseline: 1.0225x; 1.0225x over previous
#include <cuda_runtime.h>

// VolGeoNet trilinear interpolation, grid-sorted processing order for L2 reuse.
// Inputs: x [B,3] f32, grid_value [N1^3,1] f32, grid_feature [N1^3,256] f32.
// Output: concat(out [B,1], feat [B,256]) float, out first.

#define N_GRID 64
#define N1 65
#define W_FEAT 256
#define MAXB 262144
#define NBINS 32768   // (64/2)^3 coarse cells

__device__ int g_hist[NBINS];
__device__ int g_binstart[NBINS];
__device__ int g_key[MAXB];
__device__ int g_rank[MAXB];
__device__ int g_sorted[MAXB];

__device__ __forceinline__ void cell_of(const float* __restrict__ x, int p,
                                        int& ix, int& iy, int& iz)
{
    const float rx = (x[p * 3 + 0] + 1.0f) * 32.0f;
    const float ry = (x[p * 3 + 1] + 1.0f) * 32.0f;
    const float rz = (x[p * 3 + 2] + 1.0f) * 32.0f;
    ix = (int)floorf(rx); ix = ix < 0 ? 0 : (ix > N_GRID - 1 ? N_GRID - 1 : ix);
    iy = (int)floorf(ry); iy = iy < 0 ? 0 : (iy > N_GRID - 1 ? N_GRID - 1 : iy);
    iz = (int)floorf(rz); iz = iz < 0 ? 0 : (iz > N_GRID - 1 ? N_GRID - 1 : iz);
}

__global__ void zero_hist_kernel()
{
    int i = blockIdx.x * blockDim.x + threadIdx.x;
    if (i < NBINS) g_hist[i] = 0;
}

__global__ void histo_kernel(const float* __restrict__ x, int B)
{
    int p = blockIdx.x * blockDim.x + threadIdx.x;
    if (p >= B) return;
    int ix, iy, iz;
    cell_of(x, p, ix, iy, iz);
    int key = ((ix >> 1) * 32 + (iy >> 1)) * 32 + (iz >> 1);
    g_key[p] = key;
    g_rank[p] = atomicAdd(&g_hist[key], 1);
}

// Single block, 1024 threads, 32 bins each -> exclusive scan.
__global__ void __launch_bounds__(1024) scan_kernel()
{
    __shared__ int s[1024];
    const int t = threadIdx.x;
    const int base = t * 32;
    int local[32];
    int sum = 0;
#pragma unroll
    for (int i = 0; i < 32; i++) {
        local[i] = sum;
        sum += g_hist[base + i];
    }
    s[t] = sum;
    __syncthreads();
    for (int off = 1; off < 1024; off <<= 1) {
        int v = 0;
        if (t >= off) v = s[t - off];
        __syncthreads();
        if (t >= off) s[t] += v;
        __syncthreads();
    }
    const int prefix = (t == 0) ? 0 : s[t - 1];
#pragma unroll
    for (int i = 0; i < 32; i++)
        g_binstart[base + i] = prefix + local[i];
}

__global__ void scatter_kernel(int B)
{
    int p = blockIdx.x * blockDim.x + threadIdx.x;
    if (p >= B) return;
    g_sorted[g_binstart[g_key[p]] + g_rank[p]] = p;
}

__global__ void __launch_bounds__(256) trilerp_kernel(
    const float* __restrict__ x,
    const float* __restrict__ gv,
    const float* __restrict__ gf,
    float* __restrict__ out_val,   // [B]
    float* __restrict__ out_feat,  // [B, 256]
    int B, int use_sorted)
{
    const int warp_global = (blockIdx.x * blockDim.x + threadIdx.x) >> 5;
    const int lane = threadIdx.x & 31;
    if (warp_global >= B) return;

    const int p = use_sorted ? g_sorted[warp_global] : warp_global;

    // Broadcast point load (all lanes same address)
    const float px = __ldg(x + p * 3 + 0);
    const float py = __ldg(x + p * 3 + 1);
    const float pz = __ldg(x + p * 3 + 2);

    const float rx = (px + 1.0f) * 32.0f;
    const float ry = (py + 1.0f) * 32.0f;
    const float rz = (pz + 1.0f) * 32.0f;

    const bool valid = (rx >= 0.0f) && (rx <= 64.0f) &&
                       (ry >= 0.0f) && (ry <= 64.0f) &&
                       (rz >= 0.0f) && (rz <= 64.0f);
    const float vmask = valid ? 1.0f : 0.0f;

    int ix = (int)floorf(rx); ix = ix < 0 ? 0 : (ix > N_GRID - 1 ? N_GRID - 1 : ix);
    int iy = (int)floorf(ry); iy = iy < 0 ? 0 : (iy > N_GRID - 1 ? N_GRID - 1 : iy);
    int iz = (int)floorf(rz); iz = iz < 0 ? 0 : (iz > N_GRID - 1 ? N_GRID - 1 : iz);

    const float tx = rx - (float)ix;
    const float ty = ry - (float)iy;
    const float tz = rz - (float)iz;

    const int base = (ix * N1 + iy) * N1 + iz;

    const float wx0 = 1.0f - tx, wy0 = 1.0f - ty, wz0 = 1.0f - tz;
    float w[8];
    w[0] = wx0 * wy0 * wz0;
    w[1] = wx0 * wy0 * tz;
    w[2] = wx0 * ty  * wz0;
    w[3] = wx0 * ty  * tz;
    w[4] = tx  * wy0 * wz0;
    w[5] = tx  * wy0 * tz;
    w[6] = tx  * ty  * wz0;
    w[7] = tx  * ty  * tz;

    const int offs[8] = {
        0, 1, N1, N1 + 1,
        N1 * N1, N1 * N1 + 1, N1 * N1 + N1, N1 * N1 + N1 + 1
    };

    // grid_value gather: lanes 0..7 own one corner each, butterfly-reduce.
    float gvv = 0.0f;
    if (lane < 8) {
        gvv = w[lane] * __ldg(gv + (base + offs[lane]));
    }
    gvv += __shfl_xor_sync(0xffffffffu, gvv, 4);
    gvv += __shfl_xor_sync(0xffffffffu, gvv, 2);
    gvv += __shfl_xor_sync(0xffffffffu, gvv, 1);
    if (lane == 0) out_val[p] = gvv * vmask;

    float a0 = 0.f, a1 = 0.f, a2 = 0.f, a3 = 0.f;
    float b0 = 0.f, b1 = 0.f, b2 = 0.f, b3 = 0.f;

#pragma unroll
    for (int c = 0; c < 8; c++) {
        const float4* row = (const float4*)(gf + (size_t)(base + offs[c]) * W_FEAT);
        const float4 fa = __ldg(row + lane);
        const float4 fb = __ldg(row + lane + 32);
        const float wc = w[c];
        a0 = fmaf(wc, fa.x, a0);
        a1 = fmaf(wc, fa.y, a1);
        a2 = fmaf(wc, fa.z, a2);
        a3 = fmaf(wc, fa.w, a3);
        b0 = fmaf(wc, fb.x, b0);
        b1 = fmaf(wc, fb.y, b1);
        b2 = fmaf(wc, fb.z, b2);
        b3 = fmaf(wc, fb.w, b3);
    }

    float4* frow = (float4*)(out_feat + (size_t)p * W_FEAT);
    frow[lane]      = make_float4(a0 * vmask, a1 * vmask, a2 * vmask, a3 * vmask);
    frow[lane + 32] = make_float4(b0 * vmask, b1 * vmask, b2 * vmask, b3 * vmask);
}

extern "C" void kernel_launch(void* const* d_in, const int* in_sizes, int n_in,
                              void* d_out, int out_size)
{
    const float* x  = (const float*)d_in[0];
    const float* gv = (const float*)d_in[1];
    const float* gf = (const float*)d_in[2];
    float* out = (float*)d_out;

    const int B = in_sizes[0] / 3;
    float* out_val  = out;        // [B]
    float* out_feat = out + B;    // [B, 256]

    const int use_sorted = (B <= MAXB) ? 1 : 0;

    if (use_sorted) {
        zero_hist_kernel<<<(NBINS + 255) / 256, 256>>>();
        histo_kernel<<<(B + 255) / 256, 256>>>(x, B);
        scan_kernel<<<1, 1024>>>();
        scatter_kernel<<<(B + 255) / 256, 256>>>(B);
    }

    const int threads = 256;  // 8 warps = 8 points per block
    const int warps_per_block = threads / 32;
    const int blocks = (B + warps_per_block - 1) / warps_per_block;
    trilerp_kernel<<<blocks, threads>>>(x, gv, gf, out_val, out_feat, B, use_sorted);
}